// round 1
// baseline (speedup 1.0000x reference)
#include <cuda_runtime.h>
#include <cstddef>

// Problem constants
#define BATCH 8
#define DIMC  256
#define NH    8
#define HD    32
#define NPIX  1024
#define SCALE 0.17677669529663687f   // 32^-0.5

// Scratch (allocation-free rule: __device__ globals)
static __device__ float g_qkv[(size_t)BATCH * 3 * DIMC * NPIX];   // [b][3C][N]  ~24 MB
static __device__ float g_att[(size_t)BATCH * DIMC * NPIX];       // [b][C][N]   ~8 MB

// ---------------------------------------------------------------------------
// Batched GEMM: C[b][m][n] = sum_k A[m][k] * B[b][k][n] (+ bias[m])
// Block tile 64x64, K-chunks of 16, 256 threads, 4x4 register tiles.
// ---------------------------------------------------------------------------
__global__ __launch_bounds__(256) void gemm64(const float* __restrict__ A,
                                              const float* __restrict__ B,
                                              float* __restrict__ C,
                                              const float* __restrict__ bias,
                                              int M, int N, int K)
{
    __shared__ float As[16][64];   // transposed: As[k][m]
    __shared__ float Bs[16][64];   // Bs[k][n]

    const int tid = threadIdx.x;
    const int bm = blockIdx.y * 64;
    const int bn = blockIdx.x * 64;
    const float* Bb = B + (size_t)blockIdx.z * K * N;
    float* Cb = C + (size_t)blockIdx.z * M * N;

    const int ty = tid >> 4;            // 0..15
    const int tx = tid & 15;            // 0..15
    const int ar = tid >> 2;            // 0..63 (A row within tile)
    const int ac = (tid & 3) << 2;      // 0..12 (A col group)
    const int br = tid >> 4;            // 0..15 (B k row)
    const int bc = (tid & 15) << 2;     // 0..60 (B col group)

    float acc[4][4] = {};

    for (int k0 = 0; k0 < K; k0 += 16) {
        float4 av = *(const float4*)&A[(size_t)(bm + ar) * K + k0 + ac];
        As[ac + 0][ar] = av.x;
        As[ac + 1][ar] = av.y;
        As[ac + 2][ar] = av.z;
        As[ac + 3][ar] = av.w;
        *(float4*)&Bs[br][bc] = *(const float4*)&Bb[(size_t)(k0 + br) * N + bn + bc];
        __syncthreads();

        #pragma unroll
        for (int k = 0; k < 16; ++k) {
            float4 a = *(const float4*)&As[k][ty << 2];
            float4 b = *(const float4*)&Bs[k][tx << 2];
            float ax[4] = {a.x, a.y, a.z, a.w};
            float bx[4] = {b.x, b.y, b.z, b.w};
            #pragma unroll
            for (int i = 0; i < 4; ++i)
                #pragma unroll
                for (int j = 0; j < 4; ++j)
                    acc[i][j] += ax[i] * bx[j];
        }
        __syncthreads();
    }

    #pragma unroll
    for (int i = 0; i < 4; ++i) {
        const int row = bm + (ty << 2) + i;
        const float bi = bias ? bias[row] : 0.0f;
        float4 o;
        o.x = acc[i][0] + bi;
        o.y = acc[i][1] + bi;
        o.z = acc[i][2] + bi;
        o.w = acc[i][3] + bi;
        *(float4*)&Cb[(size_t)row * N + bn + (tx << 2)] = o;
    }
}

// ---------------------------------------------------------------------------
// Attention: one block = 32 queries of one (b,h).
// smem: S[32][1032] full score rows (132 KB), Q[32][32], KT/VT[32][128].
// Phase A: S = scale * Q^T K (micro-GEMM, 4q x 4m tiles)
// Phase B: row-wise softmax (8 warps x 4 rows)
// Phase C: out = S @ V^T (2q x 2d tiles, float4 LDS)
// ---------------------------------------------------------------------------
#define SLD 1032
#define ATTN_SMEM ((32 * SLD + 32 * 32 + 32 * 128) * sizeof(float))

__global__ __launch_bounds__(256) void attn_kernel()
{
    extern __shared__ float sm[];
    float* S  = sm;                  // 32 x SLD
    float* Q  = sm + 32 * SLD;       // 32 x 32   (Q[d][qi])
    float* KT = Q + 32 * 32;         // 32 x 128  (K/V tile [d][m])

    const int tid = threadIdx.x;
    const int bh = blockIdx.y;
    const int b = bh >> 3;
    const int h = bh & 7;
    const int q0 = blockIdx.x * 32;

    const float* qp = g_qkv + ((size_t)b * 768 + h * 32) * 1024;
    const float* kp = qp + (size_t)256 * 1024;
    const float* vp = qp + (size_t)512 * 1024;

    // load Q tile [d][qi]
    {
        const int qi = tid & 31;
        for (int d = tid >> 5; d < 32; d += 8)
            Q[d * 32 + qi] = qp[d * 1024 + q0 + qi];
    }

    // ---- Phase A: scores ----
    const int tq = tid >> 5;   // 0..7  -> 4 query rows
    const int tm = tid & 31;   // 0..31 -> 4 key cols
    for (int mc = 0; mc < 8; ++mc) {
        __syncthreads();
        {
            const int mm = tid & 127;
            for (int d = tid >> 7; d < 32; d += 2)
                KT[d * 128 + mm] = kp[d * 1024 + mc * 128 + mm];
        }
        __syncthreads();

        float acc[4][4] = {};
        #pragma unroll
        for (int d = 0; d < 32; ++d) {
            float4 a = *(const float4*)&Q[d * 32 + (tq << 2)];
            float4 k = *(const float4*)&KT[d * 128 + (tm << 2)];
            float ax[4] = {a.x, a.y, a.z, a.w};
            float kx[4] = {k.x, k.y, k.z, k.w};
            #pragma unroll
            for (int i = 0; i < 4; ++i)
                #pragma unroll
                for (int j = 0; j < 4; ++j)
                    acc[i][j] += ax[i] * kx[j];
        }
        #pragma unroll
        for (int i = 0; i < 4; ++i) {
            float4 o;
            o.x = acc[i][0] * SCALE;
            o.y = acc[i][1] * SCALE;
            o.z = acc[i][2] * SCALE;
            o.w = acc[i][3] * SCALE;
            *(float4*)&S[(size_t)((tq << 2) + i) * SLD + mc * 128 + (tm << 2)] = o;
        }
    }
    __syncthreads();

    // ---- Phase B: softmax per row ----
    {
        const int warp = tid >> 5;
        const int lane = tid & 31;
        #pragma unroll
        for (int rr = 0; rr < 4; ++rr) {
            float* row = &S[(size_t)(warp * 4 + rr) * SLD];
            float mx = -1e30f;
            for (int i = lane; i < 1024; i += 32) mx = fmaxf(mx, row[i]);
            #pragma unroll
            for (int o = 16; o; o >>= 1) mx = fmaxf(mx, __shfl_xor_sync(0xffffffffu, mx, o));
            float s = 0.0f;
            for (int i = lane; i < 1024; i += 32) {
                float e = __expf(row[i] - mx);
                row[i] = e;
                s += e;
            }
            #pragma unroll
            for (int o = 16; o; o >>= 1) s += __shfl_xor_sync(0xffffffffu, s, o);
            const float inv = 1.0f / s;
            for (int i = lane; i < 1024; i += 32) row[i] *= inv;
        }
    }
    __syncthreads();

    // ---- Phase C: out[d][q] = sum_m S[q][m] * V[d][m] ----
    const int qq = tid >> 4;   // 0..15 -> 2 query rows
    const int dd = tid & 15;   // 0..15 -> 2 dims
    float oacc[2][2] = {};
    for (int mc = 0; mc < 8; ++mc) {
        {
            const int mm = tid & 127;
            for (int d = tid >> 7; d < 32; d += 2)
                KT[d * 128 + mm] = vp[d * 1024 + mc * 128 + mm];
        }
        __syncthreads();

        const float* s0 = &S[(size_t)(qq * 2 + 0) * SLD + mc * 128];
        const float* s1 = &S[(size_t)(qq * 2 + 1) * SLD + mc * 128];
        const float* v0 = &KT[(dd * 2 + 0) * 128];
        const float* v1 = &KT[(dd * 2 + 1) * 128];
        #pragma unroll 8
        for (int m = 0; m < 128; m += 4) {
            float4 a0 = *(const float4*)&s0[m];
            float4 a1 = *(const float4*)&s1[m];
            float4 b0 = *(const float4*)&v0[m];
            float4 b1 = *(const float4*)&v1[m];
            oacc[0][0] += a0.x * b0.x + a0.y * b0.y + a0.z * b0.z + a0.w * b0.w;
            oacc[0][1] += a0.x * b1.x + a0.y * b1.y + a0.z * b1.z + a0.w * b1.w;
            oacc[1][0] += a1.x * b0.x + a1.y * b0.y + a1.z * b0.z + a1.w * b0.w;
            oacc[1][1] += a1.x * b1.x + a1.y * b1.y + a1.z * b1.z + a1.w * b1.w;
        }
        __syncthreads();
    }

    #pragma unroll
    for (int i = 0; i < 2; ++i)
        #pragma unroll
        for (int j = 0; j < 2; ++j)
            g_att[(size_t)((b * 8 + h) * 32 + dd * 2 + j) * 1024 + q0 + qq * 2 + i] = oacc[i][j];
}

// ---------------------------------------------------------------------------
// LePE: g_att[b][c][n] += depthwise5x5(v)[b][c][n] + lepe_b[c]
// One block per (c, b). v channel cached in smem.
// ---------------------------------------------------------------------------
__global__ __launch_bounds__(256) void lepe_kernel(const float* __restrict__ lw,
                                                   const float* __restrict__ lb)
{
    __shared__ float vch[1024];
    __shared__ float wch[25];
    const int c = blockIdx.x;
    const int b = blockIdx.y;
    const int tid = threadIdx.x;

    const float* vp = g_qkv + ((size_t)b * 768 + 512 + c) * 1024;
    for (int i = tid; i < 1024; i += 256) vch[i] = vp[i];
    if (tid < 25) wch[tid] = lw[c * 25 + tid];
    __syncthreads();

    const float bias = lb[c];
    float* ap = g_att + ((size_t)b * 256 + c) * 1024;
    for (int i = tid; i < 1024; i += 256) {
        const int hh0 = i >> 5;
        const int ww0 = i & 31;
        float s = bias;
        #pragma unroll
        for (int kh = 0; kh < 5; ++kh) {
            const int hh = hh0 + kh - 2;
            if ((unsigned)hh < 32u) {
                #pragma unroll
                for (int kw = 0; kw < 5; ++kw) {
                    const int ww = ww0 + kw - 2;
                    if ((unsigned)ww < 32u)
                        s += wch[kh * 5 + kw] * vch[hh * 32 + ww];
                }
            }
        }
        ap[i] += s;
    }
}

// ---------------------------------------------------------------------------
extern "C" void kernel_launch(void* const* d_in, const int* in_sizes, int n_in,
                              void* d_out, int out_size)
{
    const float* x      = (const float*)d_in[0];
    const float* qkv_w  = (const float*)d_in[1];
    const float* proj_w = (const float*)d_in[2];
    const float* proj_b = (const float*)d_in[3];
    const float* lepe_w = (const float*)d_in[4];
    const float* lepe_b = (const float*)d_in[5];
    float* out = (float*)d_out;

    float* qkv_p = nullptr;
    float* att_p = nullptr;
    cudaGetSymbolAddress((void**)&qkv_p, g_qkv);
    cudaGetSymbolAddress((void**)&att_p, g_att);

    cudaFuncSetAttribute(attn_kernel, cudaFuncAttributeMaxDynamicSharedMemorySize,
                         (int)ATTN_SMEM);

    // 1) QKV = qkv_w @ x   (M=768, N=1024, K=256, batch 8)
    gemm64<<<dim3(16, 12, 8), 256>>>(qkv_w, x, qkv_p, nullptr, 768, 1024, 256);

    // 2) attention -> g_att  (32 q-tiles x 64 (b,h))
    attn_kernel<<<dim3(32, 64), 256, ATTN_SMEM>>>();

    // 3) LePE depthwise + bias, accumulated into g_att
    lepe_kernel<<<dim3(256, 8), 256>>>(lepe_w, lepe_b);

    // 4) out = proj_w @ g_att + proj_b  (M=256, N=1024, K=256, batch 8)
    gemm64<<<dim3(16, 4, 8), 256>>>(proj_w, att_p, out, proj_b, 256, 1024, 256);
}

// round 2
// speedup vs baseline: 3.6761x; 3.6761x over previous
#include <cuda_runtime.h>
#include <cstddef>

#define BATCH 8
#define DIMC  256
#define NPIX  1024
#define SCALE 0.17677669529663687f   // 32^-0.5

static __device__ float g_qkv[(size_t)BATCH * 3 * DIMC * NPIX];   // [b][3C][N]
static __device__ float g_att[(size_t)BATCH * DIMC * NPIX];       // [b][C][N]

// ---------------------------------------------------------------------------
// Batched GEMM: C[b][m][n] = sum_k A[m][k]*B[b][k][n] (+bias[m])
// Tile 128(M) x 64(N), K-chunks of 16, 256 threads, 8x4 register tiles.
// ---------------------------------------------------------------------------
__global__ __launch_bounds__(256) void gemm128(const float* __restrict__ A,
                                               const float* __restrict__ B,
                                               float* __restrict__ C,
                                               const float* __restrict__ bias,
                                               int M, int N, int K)
{
    __shared__ float As[16][132];   // [k][m], padded
    __shared__ float Bs[16][64];    // [k][n]

    const int tid = threadIdx.x;
    const int bm = blockIdx.y * 128;
    const int bn = blockIdx.x * 64;
    const float* Bb = B + (size_t)blockIdx.z * K * N;
    float* Cb = C + (size_t)blockIdx.z * M * N;

    const int am = tid >> 1;            // 0..127
    const int ak = (tid & 1) * 8;       // 0 or 8
    const int br = tid >> 4;            // 0..15
    const int bc = (tid & 15) << 2;     // 0..60
    const int tm = (tid >> 4) << 3;     // 0..120 step 8
    const int tn = (tid & 15) << 2;     // 0..60 step 4

    float acc[8][4] = {};

    for (int k0 = 0; k0 < K; k0 += 16) {
        float4 a0 = *(const float4*)&A[(size_t)(bm + am) * K + k0 + ak];
        float4 a1 = *(const float4*)&A[(size_t)(bm + am) * K + k0 + ak + 4];
        As[ak + 0][am] = a0.x; As[ak + 1][am] = a0.y;
        As[ak + 2][am] = a0.z; As[ak + 3][am] = a0.w;
        As[ak + 4][am] = a1.x; As[ak + 5][am] = a1.y;
        As[ak + 6][am] = a1.z; As[ak + 7][am] = a1.w;
        *(float4*)&Bs[br][bc] = *(const float4*)&Bb[(size_t)(k0 + br) * N + bn + bc];
        __syncthreads();

        #pragma unroll
        for (int k = 0; k < 16; ++k) {
            float4 x0 = *(const float4*)&As[k][tm];
            float4 x1 = *(const float4*)&As[k][tm + 4];
            float4 y  = *(const float4*)&Bs[k][tn];
            float ax[8] = {x0.x, x0.y, x0.z, x0.w, x1.x, x1.y, x1.z, x1.w};
            float by[4] = {y.x, y.y, y.z, y.w};
            #pragma unroll
            for (int i = 0; i < 8; ++i)
                #pragma unroll
                for (int j = 0; j < 4; ++j)
                    acc[i][j] += ax[i] * by[j];
        }
        __syncthreads();
    }

    #pragma unroll
    for (int i = 0; i < 8; ++i) {
        const int row = bm + tm + i;
        const float bi = bias ? bias[row] : 0.0f;
        float4 o;
        o.x = acc[i][0] + bi; o.y = acc[i][1] + bi;
        o.z = acc[i][2] + bi; o.w = acc[i][3] + bi;
        *(float4*)&Cb[(size_t)row * N + bn + tn] = o;
    }
}

// ---------------------------------------------------------------------------
// Flash attention: block = 64 queries of one (b,h); stream 16 chunks of 64 keys.
// smem 41KB -> ~4 CTA/SM. Online softmax, no global S.
// ---------------------------------------------------------------------------
__global__ __launch_bounds__(256) void attn_kernel()
{
    __shared__ float Qs[32 * 64];    // [d][q], pre-scaled by SCALE
    __shared__ float Ks[32 * 64];    // [d][m]
    __shared__ float Vs[32 * 65];    // [d][m], padded
    __shared__ float Ps[64 * 68];    // [m][q], padded; also output staging

    const int tid = threadIdx.x;
    const int bh = blockIdx.y;                 // 0..63  (b*8+h)
    const int q0 = blockIdx.x * 64;

    const float* qp = g_qkv + ((size_t)(bh >> 3) * 768 + (bh & 7) * 32) * 1024;
    const float* kp = qp + (size_t)256 * 1024;
    const float* vp = qp + (size_t)512 * 1024;

    const int ldr = tid >> 4;        // 0..15 (row for cooperative loads)
    const int ldc = (tid & 15) << 2; // 0..60

    // Load Q once, fold in softmax scale
    #pragma unroll
    for (int r = 0; r < 2; ++r) {
        const int d = ldr + r * 16;
        float4 v = *(const float4*)&qp[(size_t)d * 1024 + q0 + ldc];
        v.x *= SCALE; v.y *= SCALE; v.z *= SCALE; v.w *= SCALE;
        *(float4*)&Qs[d * 64 + ldc] = v;
    }

    const int qg = (tid >> 4) << 2;  // query group base (0..60 step 4)
    const int mg = (tid & 15) << 2;  // key-col group base (S phase)
    const int d0 = (tid & 15) * 2;   // dim pair base (O phase)

    float row_max[4] = {-1e30f, -1e30f, -1e30f, -1e30f};
    float row_sum[4] = {};
    float oacc[4][2] = {};

    for (int mc = 0; mc < 16; ++mc) {
        const int m0 = mc * 64;
        // load K, V tiles
        #pragma unroll
        for (int r = 0; r < 2; ++r) {
            const int d = ldr + r * 16;
            *(float4*)&Ks[d * 64 + ldc] = *(const float4*)&kp[(size_t)d * 1024 + m0 + ldc];
            float4 v = *(const float4*)&vp[(size_t)d * 1024 + m0 + ldc];
            Vs[d * 65 + ldc + 0] = v.x; Vs[d * 65 + ldc + 1] = v.y;
            Vs[d * 65 + ldc + 2] = v.z; Vs[d * 65 + ldc + 3] = v.w;
        }
        __syncthreads();

        // S = Q^T K  (4q x 4m per thread)
        float acc[4][4] = {};
        #pragma unroll
        for (int d = 0; d < 32; ++d) {
            float4 a = *(const float4*)&Qs[d * 64 + qg];
            float4 k = *(const float4*)&Ks[d * 64 + mg];
            float ax[4] = {a.x, a.y, a.z, a.w};
            float kx[4] = {k.x, k.y, k.z, k.w};
            #pragma unroll
            for (int i = 0; i < 4; ++i)
                #pragma unroll
                for (int j = 0; j < 4; ++j)
                    acc[i][j] += ax[i] * kx[j];
        }

        // online softmax update + write P[m][q]
        #pragma unroll
        for (int i = 0; i < 4; ++i) {
            float mx = fmaxf(fmaxf(acc[i][0], acc[i][1]), fmaxf(acc[i][2], acc[i][3]));
            #pragma unroll
            for (int o = 1; o < 16; o <<= 1)
                mx = fmaxf(mx, __shfl_xor_sync(0xffffffffu, mx, o));
            const float nm = fmaxf(row_max[i], mx);
            const float f = __expf(row_max[i] - nm);
            row_max[i] = nm;
            float p0 = __expf(acc[i][0] - nm);
            float p1 = __expf(acc[i][1] - nm);
            float p2 = __expf(acc[i][2] - nm);
            float p3 = __expf(acc[i][3] - nm);
            row_sum[i] = row_sum[i] * f + (p0 + p1 + p2 + p3);
            oacc[i][0] *= f; oacc[i][1] *= f;
            Ps[(mg + 0) * 68 + qg + i] = p0;
            Ps[(mg + 1) * 68 + qg + i] = p1;
            Ps[(mg + 2) * 68 + qg + i] = p2;
            Ps[(mg + 3) * 68 + qg + i] = p3;
        }
        __syncthreads();

        // O += P V^T  (4q x 2d per thread; P broadcast, V conflict-free)
        const float* v0p = &Vs[(d0 + 0) * 65];
        const float* v1p = &Vs[(d0 + 1) * 65];
        #pragma unroll 4
        for (int m = 0; m < 64; ++m) {
            float4 p = *(const float4*)&Ps[m * 68 + qg];
            float v0 = v0p[m], v1 = v1p[m];
            oacc[0][0] += p.x * v0; oacc[0][1] += p.x * v1;
            oacc[1][0] += p.y * v0; oacc[1][1] += p.y * v1;
            oacc[2][0] += p.z * v0; oacc[2][1] += p.z * v1;
            oacc[3][0] += p.w * v0; oacc[3][1] += p.w * v1;
        }
        __syncthreads();
    }

    // normalize
    #pragma unroll
    for (int i = 0; i < 4; ++i) {
        float rs = row_sum[i];
        #pragma unroll
        for (int o = 1; o < 16; o <<= 1)
            rs += __shfl_xor_sync(0xffffffffu, rs, o);
        const float inv = 1.0f / rs;
        oacc[i][0] *= inv; oacc[i][1] *= inv;
    }

    // stage O[d][q] in Ps, then coalesced store
    #pragma unroll
    for (int i = 0; i < 4; ++i) {
        Ps[(d0 + 0) * 68 + qg + i] = oacc[i][0];
        Ps[(d0 + 1) * 68 + qg + i] = oacc[i][1];
    }
    __syncthreads();
    #pragma unroll
    for (int r = 0; r < 2; ++r) {
        const int d = ldr + r * 16;
        *(float4*)&g_att[((size_t)bh * 32 + d) * 1024 + q0 + ldc] =
            *(const float4*)&Ps[d * 68 + ldc];
    }
}

// ---------------------------------------------------------------------------
// LePE: g_att[b][c][n] += depthwise5x5(v)[b][c][n] + lepe_b[c]
// ---------------------------------------------------------------------------
__global__ __launch_bounds__(256) void lepe_kernel(const float* __restrict__ lw,
                                                   const float* __restrict__ lb)
{
    __shared__ float vch[1024];
    __shared__ float wch[25];
    const int c = blockIdx.x;
    const int b = blockIdx.y;
    const int tid = threadIdx.x;

    const float* vp = g_qkv + ((size_t)b * 768 + 512 + c) * 1024;
    for (int i = tid; i < 1024; i += 256) vch[i] = vp[i];
    if (tid < 25) wch[tid] = lw[c * 25 + tid];
    __syncthreads();

    const float bias = lb[c];
    float* ap = g_att + ((size_t)b * 256 + c) * 1024;
    for (int i = tid; i < 1024; i += 256) {
        const int hh0 = i >> 5;
        const int ww0 = i & 31;
        float s = bias;
        #pragma unroll
        for (int kh = 0; kh < 5; ++kh) {
            const int hh = hh0 + kh - 2;
            if ((unsigned)hh < 32u) {
                #pragma unroll
                for (int kw = 0; kw < 5; ++kw) {
                    const int ww = ww0 + kw - 2;
                    if ((unsigned)ww < 32u)
                        s += wch[kh * 5 + kw] * vch[hh * 32 + ww];
                }
            }
        }
        ap[i] += s;
    }
}

// ---------------------------------------------------------------------------
extern "C" void kernel_launch(void* const* d_in, const int* in_sizes, int n_in,
                              void* d_out, int out_size)
{
    const float* x      = (const float*)d_in[0];
    const float* qkv_w  = (const float*)d_in[1];
    const float* proj_w = (const float*)d_in[2];
    const float* proj_b = (const float*)d_in[3];
    const float* lepe_w = (const float*)d_in[4];
    const float* lepe_b = (const float*)d_in[5];
    float* out = (float*)d_out;

    float* qkv_p = nullptr;
    float* att_p = nullptr;
    cudaGetSymbolAddress((void**)&qkv_p, g_qkv);
    cudaGetSymbolAddress((void**)&att_p, g_att);

    // 1) QKV = qkv_w @ x   (M=768, N=1024, K=256, batch 8)
    gemm128<<<dim3(16, 6, 8), 256>>>(qkv_w, x, qkv_p, nullptr, 768, 1024, 256);

    // 2) flash attention -> g_att  (16 q-tiles x 64 (b,h))
    attn_kernel<<<dim3(16, 64), 256>>>();

    // 3) LePE depthwise + bias accumulated into g_att
    lepe_kernel<<<dim3(256, 8), 256>>>(lepe_w, lepe_b);

    // 4) out = proj_w @ g_att + proj_b  (M=256, N=1024, K=256, batch 8)
    gemm128<<<dim3(16, 2, 8), 256>>>(proj_w, att_p, out, proj_b, 256, 1024, 256);
}

// round 3
// speedup vs baseline: 5.9002x; 1.6050x over previous
#include <cuda_runtime.h>
#include <cstdint>
#include <cstddef>

#define SCALE 0.17677669529663687f   // 32^-0.5

// ---------------- scratch (allocation-free rule) ----------------
static __device__ float g_xT  [(size_t)8 * 1024 * 256];   // x transposed  [b][n][c]
static __device__ float g_qkv [(size_t)8 * 768 * 1024];   // qkv           [b][3C][n]
static __device__ float g_qkT [(size_t)8 * 1024 * 512];   // q,k transposed[b][n][512]
static __device__ float g_attT[(size_t)8 * 1024 * 256];   // attn out      [b][n][c]

// ---------------- helpers ----------------
__device__ __forceinline__ uint32_t f2tf(float x) {
    uint32_t r; asm("cvt.rna.tf32.f32 %0, %1;" : "=r"(r) : "f"(x)); return r;
}
__device__ __forceinline__ void split_tf(float x, float& hi, float& lo) {
    uint32_t h = f2tf(x);
    float hf = __uint_as_float(h);
    hi = hf;
    lo = __uint_as_float(f2tf(x - hf));
}
// D += A(16x8,row) * B(8x8,col)  tf32
__device__ __forceinline__ void mma8(float* d, const uint32_t* a, const uint32_t* b) {
    asm volatile(
        "mma.sync.aligned.m16n8k8.row.col.f32.tf32.tf32.f32 "
        "{%0,%1,%2,%3}, {%4,%5,%6,%7}, {%8,%9}, {%0,%1,%2,%3};"
        : "+f"(d[0]), "+f"(d[1]), "+f"(d[2]), "+f"(d[3])
        : "r"(a[0]), "r"(a[1]), "r"(a[2]), "r"(a[3]), "r"(b[0]), "r"(b[1]));
}

// ---------------------------------------------------------------------------
// 32x32 tile transpose: out[b][n][c] = in[b][c][n]   (n-dim = 1024 fixed)
// ---------------------------------------------------------------------------
__global__ __launch_bounds__(256) void transpose32(const float* __restrict__ in,
                                                   float* __restrict__ out,
                                                   int C, size_t ibs, size_t obs)
{
    __shared__ float s[32 * 33];
    const int n0 = blockIdx.x * 32;
    const int c0 = blockIdx.y * 32;
    const int b  = blockIdx.z;
    const int w = threadIdx.x >> 5, lane = threadIdx.x & 31;
    const float* ip = in + (size_t)b * ibs;
    float* op = out + (size_t)b * obs;
    #pragma unroll
    for (int i = 0; i < 4; ++i) {
        const int cc = w * 4 + i;
        s[lane * 33 + cc] = ip[(size_t)(c0 + cc) * 1024 + n0 + lane];
    }
    __syncthreads();
    #pragma unroll
    for (int i = 0; i < 4; ++i) {
        const int nn = w * 4 + i;
        op[(size_t)(n0 + nn) * C + c0 + lane] = s[nn * 33 + lane];
    }
}

// ---------------------------------------------------------------------------
// tf32 split GEMM: C[b][m][n] = sum_k A[m][k] * Bt[b][n][k]  (+bias[m])
// K=256, N=1024 fixed. Block: 64x64 tile, 128 threads (4 warps x 16 rows).
// ---------------------------------------------------------------------------
__global__ __launch_bounds__(128) void gemm_tf32(const float* __restrict__ A,
                                                 const float* __restrict__ Bt,
                                                 float* __restrict__ C,
                                                 const float* __restrict__ bias,
                                                 int M)
{
    __shared__ float sm[4 * 2304];
    float* Ah = sm;
    float* Al = sm + 2304;
    float* Bh = sm + 4608;
    float* Bl = sm + 6912;

    const int tid = threadIdx.x;
    const int bm = blockIdx.y * 64, bn = blockIdx.x * 64, b = blockIdx.z;
    const float* Btb = Bt + (size_t)b * 1024 * 256;
    float* Cb = C + (size_t)b * M * 1024;

    const int lane = tid & 31, wrp = tid >> 5;
    const int g = lane >> 2, t = lane & 3;
    const int qb = wrp * 16;

    float cf[8][4] = {};

    for (int kc = 0; kc < 8; ++kc) {
        const int k0 = kc * 32;
        #pragma unroll
        for (int i = 0; i < 4; ++i) {
            const int m  = (tid >> 3) + i * 16;
            const int kq = (tid & 7) * 4;
            float4 av = *(const float4*)&A[(size_t)(bm + m) * 256 + k0 + kq];
            float4 bv = *(const float4*)&Btb[(size_t)(bn + m) * 256 + k0 + kq];
            float4 ah, al, bh, bl;
            split_tf(av.x, ah.x, al.x); split_tf(av.y, ah.y, al.y);
            split_tf(av.z, ah.z, al.z); split_tf(av.w, ah.w, al.w);
            split_tf(bv.x, bh.x, bl.x); split_tf(bv.y, bh.y, bl.y);
            split_tf(bv.z, bh.z, bl.z); split_tf(bv.w, bh.w, bl.w);
            *(float4*)&Ah[m * 36 + kq] = ah; *(float4*)&Al[m * 36 + kq] = al;
            *(float4*)&Bh[m * 36 + kq] = bh; *(float4*)&Bl[m * 36 + kq] = bl;
        }
        __syncthreads();

        #pragma unroll
        for (int kk = 0; kk < 4; ++kk) {
            const int r1 = (qb + g) * 36 + kk * 8 + t;
            const int r2 = r1 + 8 * 36;
            uint32_t ahr[4], alr[4];
            ahr[0] = __float_as_uint(Ah[r1]);     ahr[1] = __float_as_uint(Ah[r2]);
            ahr[2] = __float_as_uint(Ah[r1 + 4]); ahr[3] = __float_as_uint(Ah[r2 + 4]);
            alr[0] = __float_as_uint(Al[r1]);     alr[1] = __float_as_uint(Al[r2]);
            alr[2] = __float_as_uint(Al[r1 + 4]); alr[3] = __float_as_uint(Al[r2 + 4]);
            #pragma unroll
            for (int nt = 0; nt < 8; ++nt) {
                const int bb = (nt * 8 + g) * 36 + kk * 8 + t;
                uint32_t bhr[2], blr[2];
                bhr[0] = __float_as_uint(Bh[bb]); bhr[1] = __float_as_uint(Bh[bb + 4]);
                blr[0] = __float_as_uint(Bl[bb]); blr[1] = __float_as_uint(Bl[bb + 4]);
                mma8(cf[nt], ahr, bhr);
                mma8(cf[nt], alr, bhr);
                mma8(cf[nt], ahr, blr);
            }
        }
        __syncthreads();
    }

    // epilogue: stage to smem, coalesced store
    float* Cs = sm;   // 64 x 68
    const int row1 = qb + g, row2 = row1 + 8;
    const float bi1 = bias ? bias[bm + row1] : 0.0f;
    const float bi2 = bias ? bias[bm + row2] : 0.0f;
    #pragma unroll
    for (int nt = 0; nt < 8; ++nt) {
        *(float2*)&Cs[row1 * 68 + nt * 8 + 2 * t] = make_float2(cf[nt][0] + bi1, cf[nt][1] + bi1);
        *(float2*)&Cs[row2 * 68 + nt * 8 + 2 * t] = make_float2(cf[nt][2] + bi2, cf[nt][3] + bi2);
    }
    __syncthreads();
    #pragma unroll
    for (int ii = 0; ii < 8; ++ii) {
        const int flat = ii * 128 + tid;
        const int m = flat >> 4, n4 = (flat & 15) * 4;
        *(float4*)&Cb[(size_t)(bm + m) * 1024 + bn + n4] = *(const float4*)&Cs[m * 68 + n4];
    }
}

// ---------------------------------------------------------------------------
// Flash attention, tf32 split mma. Block = 64 queries of one (b,h), 128 thr.
// Q/K from g_qkT ([n][512]), V from g_qkv ([c][n]). Out -> g_attT [n][256].
// ---------------------------------------------------------------------------
#define ATTN_SMEM (17920 * sizeof(float))
__global__ __launch_bounds__(128) void attn_kernel()
{
    extern __shared__ float sa[];
    float* Qh = sa;            // 64 x 36
    float* Ql = Qh + 2304;
    float* Kh = Ql + 2304;     // 64 x 36
    float* Kl = Kh + 2304;
    float* Vh = Kl + 2304;     // 32 x 68
    float* Vl = Vh + 2176;
    float* Ps = Vl + 2176;     // 64 x 68  (P, later O staging)

    const int tid = threadIdx.x;
    const int bh = blockIdx.y;
    const int b = bh >> 3, h = bh & 7;
    const int q0 = blockIdx.x * 64;

    const float* qkTb = g_qkT + (size_t)b * 1024 * 512;
    const float* vp   = g_qkv + ((size_t)b * 768 + 512 + h * 32) * 1024;

    const int lane = tid & 31, wrp = tid >> 5;
    const int g = lane >> 2, t = lane & 3;
    const int qb = wrp * 16;

    // load Q (scaled) once
    #pragma unroll
    for (int i = 0; i < 4; ++i) {
        const int q = (tid >> 3) + i * 16;
        const int d4 = (tid & 7) * 4;
        float4 v = *(const float4*)&qkTb[(size_t)(q0 + q) * 512 + h * 32 + d4];
        v.x *= SCALE; v.y *= SCALE; v.z *= SCALE; v.w *= SCALE;
        float4 hi, lo;
        split_tf(v.x, hi.x, lo.x); split_tf(v.y, hi.y, lo.y);
        split_tf(v.z, hi.z, lo.z); split_tf(v.w, hi.w, lo.w);
        *(float4*)&Qh[q * 36 + d4] = hi;
        *(float4*)&Ql[q * 36 + d4] = lo;
    }

    float rm[2] = {-1e30f, -1e30f};
    float rs[2] = {0.0f, 0.0f};
    float oacc[4][4] = {};

    for (int mc = 0; mc < 16; ++mc) {
        const int m0 = mc * 64;
        __syncthreads();
        // K tile [m][d]
        #pragma unroll
        for (int i = 0; i < 4; ++i) {
            const int m = (tid >> 3) + i * 16;
            const int d4 = (tid & 7) * 4;
            float4 v = *(const float4*)&qkTb[(size_t)(m0 + m) * 512 + 256 + h * 32 + d4];
            float4 hi, lo;
            split_tf(v.x, hi.x, lo.x); split_tf(v.y, hi.y, lo.y);
            split_tf(v.z, hi.z, lo.z); split_tf(v.w, hi.w, lo.w);
            *(float4*)&Kh[m * 36 + d4] = hi;
            *(float4*)&Kl[m * 36 + d4] = lo;
        }
        // V tile [d][m]
        #pragma unroll
        for (int i = 0; i < 4; ++i) {
            const int d = (tid >> 4) + i * 8;
            const int m4 = (tid & 15) * 4;
            float4 v = *(const float4*)&vp[(size_t)d * 1024 + m0 + m4];
            float4 hi, lo;
            split_tf(v.x, hi.x, lo.x); split_tf(v.y, hi.y, lo.y);
            split_tf(v.z, hi.z, lo.z); split_tf(v.w, hi.w, lo.w);
            *(float4*)&Vh[d * 68 + m4] = hi;
            *(float4*)&Vl[d * 68 + m4] = lo;
        }
        __syncthreads();

        // S = Q^T K
        float sf[8][4] = {};
        #pragma unroll
        for (int kk = 0; kk < 4; ++kk) {
            const int r1 = (qb + g) * 36 + kk * 8 + t;
            const int r2 = r1 + 8 * 36;
            uint32_t ah[4], al[4];
            ah[0] = __float_as_uint(Qh[r1]);     ah[1] = __float_as_uint(Qh[r2]);
            ah[2] = __float_as_uint(Qh[r1 + 4]); ah[3] = __float_as_uint(Qh[r2 + 4]);
            al[0] = __float_as_uint(Ql[r1]);     al[1] = __float_as_uint(Ql[r2]);
            al[2] = __float_as_uint(Ql[r1 + 4]); al[3] = __float_as_uint(Ql[r2 + 4]);
            #pragma unroll
            for (int nt = 0; nt < 8; ++nt) {
                const int bb = (nt * 8 + g) * 36 + kk * 8 + t;
                uint32_t bhr[2], blr[2];
                bhr[0] = __float_as_uint(Kh[bb]); bhr[1] = __float_as_uint(Kh[bb + 4]);
                blr[0] = __float_as_uint(Kl[bb]); blr[1] = __float_as_uint(Kl[bb + 4]);
                mma8(sf[nt], ah, bhr);
                mma8(sf[nt], al, bhr);
                mma8(sf[nt], ah, blr);
            }
        }

        // online softmax (rows qb+g and qb+g+8)
        float m1 = -1e30f, m2 = -1e30f;
        #pragma unroll
        for (int nt = 0; nt < 8; ++nt) {
            m1 = fmaxf(m1, fmaxf(sf[nt][0], sf[nt][1]));
            m2 = fmaxf(m2, fmaxf(sf[nt][2], sf[nt][3]));
        }
        m1 = fmaxf(m1, __shfl_xor_sync(0xffffffffu, m1, 1));
        m1 = fmaxf(m1, __shfl_xor_sync(0xffffffffu, m1, 2));
        m2 = fmaxf(m2, __shfl_xor_sync(0xffffffffu, m2, 1));
        m2 = fmaxf(m2, __shfl_xor_sync(0xffffffffu, m2, 2));
        const float nm1 = fmaxf(rm[0], m1), nm2 = fmaxf(rm[1], m2);
        const float f1 = __expf(rm[0] - nm1), f2 = __expf(rm[1] - nm2);
        rm[0] = nm1; rm[1] = nm2;
        float cs1 = 0.0f, cs2 = 0.0f;
        #pragma unroll
        for (int nt = 0; nt < 8; ++nt) {
            float p0 = __expf(sf[nt][0] - nm1);
            float p1 = __expf(sf[nt][1] - nm1);
            float p2 = __expf(sf[nt][2] - nm2);
            float p3 = __expf(sf[nt][3] - nm2);
            cs1 += p0 + p1; cs2 += p2 + p3;
            *(float2*)&Ps[(qb + g) * 68 + nt * 8 + 2 * t] =
                make_float2(__uint_as_float(f2tf(p0)), __uint_as_float(f2tf(p1)));
            *(float2*)&Ps[(qb + g + 8) * 68 + nt * 8 + 2 * t] =
                make_float2(__uint_as_float(f2tf(p2)), __uint_as_float(f2tf(p3)));
        }
        cs1 += __shfl_xor_sync(0xffffffffu, cs1, 1);
        cs1 += __shfl_xor_sync(0xffffffffu, cs1, 2);
        cs2 += __shfl_xor_sync(0xffffffffu, cs2, 1);
        cs2 += __shfl_xor_sync(0xffffffffu, cs2, 2);
        rs[0] = rs[0] * f1 + cs1;
        rs[1] = rs[1] * f2 + cs2;
        #pragma unroll
        for (int nt = 0; nt < 4; ++nt) {
            oacc[nt][0] *= f1; oacc[nt][1] *= f1;
            oacc[nt][2] *= f2; oacc[nt][3] *= f2;
        }
        __syncwarp();

        // O += P V^T
        #pragma unroll
        for (int kk = 0; kk < 8; ++kk) {
            const int r1 = (qb + g) * 68 + kk * 8 + t;
            const int r2 = r1 + 8 * 68;
            uint32_t pa[4];
            pa[0] = __float_as_uint(Ps[r1]);     pa[1] = __float_as_uint(Ps[r2]);
            pa[2] = __float_as_uint(Ps[r1 + 4]); pa[3] = __float_as_uint(Ps[r2 + 4]);
            #pragma unroll
            for (int nt = 0; nt < 4; ++nt) {
                const int vb = (nt * 8 + g) * 68 + kk * 8 + t;
                uint32_t bhr[2], blr[2];
                bhr[0] = __float_as_uint(Vh[vb]); bhr[1] = __float_as_uint(Vh[vb + 4]);
                blr[0] = __float_as_uint(Vl[vb]); blr[1] = __float_as_uint(Vl[vb + 4]);
                mma8(oacc[nt], pa, bhr);
                mma8(oacc[nt], pa, blr);
            }
        }
        __syncwarp();
    }

    // normalize + stage O[q][d] then coalesced store to attT
    __syncthreads();
    const float inv1 = 1.0f / rs[0], inv2 = 1.0f / rs[1];
    float* Os = Ps;   // 64 x 36
    #pragma unroll
    for (int nt = 0; nt < 4; ++nt) {
        *(float2*)&Os[(qb + g) * 36 + nt * 8 + 2 * t] =
            make_float2(oacc[nt][0] * inv1, oacc[nt][1] * inv1);
        *(float2*)&Os[(qb + g + 8) * 36 + nt * 8 + 2 * t] =
            make_float2(oacc[nt][2] * inv2, oacc[nt][3] * inv2);
    }
    __syncthreads();
    #pragma unroll
    for (int i = 0; i < 4; ++i) {
        const int flat = i * 128 + tid;
        const int q = flat >> 3, d4 = (flat & 7) * 4;
        *(float4*)&g_attT[((size_t)b * 1024 + q0 + q) * 256 + h * 32 + d4] =
            *(const float4*)&Os[q * 36 + d4];
    }
}

// ---------------------------------------------------------------------------
// LePE: attT[b][n][c] += dwconv5x5(v)[c][n] + lepe_b[c]
// Block = (cgroup 64ch, rowband 4rows, batch). Coalesced channel-contig RMW.
// ---------------------------------------------------------------------------
#define LEPE_SMEM (20160 * sizeof(float))
__global__ __launch_bounds__(256) void lepe_kernel(const float* __restrict__ lw,
                                                   const float* __restrict__ lb)
{
    extern __shared__ float ls[];
    float* sv  = ls;            // 64 x 289 (8 rows x 36 cols, c-stride 289)
    float* wch = ls + 64 * 289; // 64 x 25
    float* bch = wch + 1600;    // 64

    const int cg = blockIdx.x, rb = blockIdx.y, b = blockIdx.z;
    const int tid = threadIdx.x;

    for (int i = tid; i < 1600; i += 256) wch[i] = lw[cg * 64 * 25 + i];
    if (tid < 64) bch[tid] = lb[cg * 64 + tid];
    // zero pad columns (0,1,34,35)
    for (int i = tid; i < 64 * 8 * 4; i += 256) {
        const int c = i >> 5, rsd = (i >> 2) & 7, e = i & 3;
        const int col = (e < 2) ? e : 32 + e;
        sv[c * 289 + rsd * 36 + col] = 0.0f;
    }
    // load v rows [rb*4-2, rb*4+6)
    const float* vbase = g_qkv + ((size_t)b * 768 + 512 + cg * 64) * 1024;
    for (int i = tid; i < 4096; i += 256) {
        const int c = i >> 6, rsd = (i >> 3) & 7, q4 = (i & 7) * 4;
        const int gr = rb * 4 - 2 + rsd;
        float4 v = make_float4(0.f, 0.f, 0.f, 0.f);
        if ((unsigned)gr < 32u)
            v = *(const float4*)&vbase[(size_t)c * 1024 + gr * 32 + q4];
        float* p = &sv[c * 289 + rsd * 36 + 2 + q4];
        p[0] = v.x; p[1] = v.y; p[2] = v.z; p[3] = v.w;
    }
    __syncthreads();

    const int c = tid & 63, r = tid >> 6;
    const float* svc = &sv[c * 289];
    const float* wc = &wch[c * 25];
    const float bias = bch[c];
    float* op = g_attT + ((size_t)b * 1024 + (rb * 4 + r) * 32) * 256 + cg * 64 + c;
    for (int col = 0; col < 32; ++col) {
        float acc = bias;
        #pragma unroll
        for (int kh = 0; kh < 5; ++kh)
            #pragma unroll
            for (int kw = 0; kw < 5; ++kw)
                acc += wc[kh * 5 + kw] * svc[(r + kh) * 36 + col + kw];
        op[(size_t)col * 256] += acc;
    }
}

// ---------------------------------------------------------------------------
extern "C" void kernel_launch(void* const* d_in, const int* in_sizes, int n_in,
                              void* d_out, int out_size)
{
    const float* x      = (const float*)d_in[0];
    const float* qkv_w  = (const float*)d_in[1];
    const float* proj_w = (const float*)d_in[2];
    const float* proj_b = (const float*)d_in[3];
    const float* lepe_w = (const float*)d_in[4];
    const float* lepe_b = (const float*)d_in[5];
    float* out = (float*)d_out;

    float *xT_p, *qkv_p, *attT_p;
    cudaGetSymbolAddress((void**)&xT_p, g_xT);
    cudaGetSymbolAddress((void**)&qkv_p, g_qkv);
    cudaGetSymbolAddress((void**)&attT_p, g_attT);
    float* qkT_p; cudaGetSymbolAddress((void**)&qkT_p, g_qkT);

    cudaFuncSetAttribute(attn_kernel, cudaFuncAttributeMaxDynamicSharedMemorySize, (int)ATTN_SMEM);
    cudaFuncSetAttribute(lepe_kernel, cudaFuncAttributeMaxDynamicSharedMemorySize, (int)LEPE_SMEM);

    // 1) xT = transpose(x)
    transpose32<<<dim3(32, 8, 8), 256>>>(x, xT_p, 256, (size_t)256 * 1024, (size_t)1024 * 256);
    // 2) qkv = qkv_w @ x
    gemm_tf32<<<dim3(16, 12, 8), 128>>>(qkv_w, xT_p, qkv_p, nullptr, 768);
    // 3) transpose q,k channels
    transpose32<<<dim3(32, 16, 8), 256>>>(qkv_p, qkT_p, 512, (size_t)768 * 1024, (size_t)1024 * 512);
    // 4) attention -> attT
    attn_kernel<<<dim3(16, 64), 128, ATTN_SMEM>>>();
    // 5) LePE accumulate into attT
    lepe_kernel<<<dim3(4, 8, 8), 256, LEPE_SMEM>>>(lepe_w, lepe_b);
    // 6) out = proj_w @ att + proj_b
    gemm_tf32<<<dim3(16, 4, 8), 128>>>(proj_w, attT_p, out, proj_b, 256);
}

// round 4
// speedup vs baseline: 9.5450x; 1.6177x over previous
#include <cuda_runtime.h>
#include <cstdint>
#include <cstddef>

#define SCALE 0.17677669529663687f   // 32^-0.5

// ---------------- scratch (allocation-free rule) ----------------
static __device__ float g_qkT [(size_t)8 * 1024 * 512];   // q,k transposed [b][n][512]
static __device__ float g_v   [(size_t)8 * 256 * 1024];   // v              [b][c][n]
static __device__ float g_attT[(size_t)8 * 1024 * 256];   // attn out       [b][n][c]

// ---------------- helpers ----------------
__device__ __forceinline__ uint32_t f2tf(float x) {
    uint32_t r; asm("cvt.rna.tf32.f32 %0, %1;" : "=r"(r) : "f"(x)); return r;
}
__device__ __forceinline__ float tf(float x) { return __uint_as_float(f2tf(x)); }

// D += A(16x8,row) * B(8x8,col)  tf32
__device__ __forceinline__ void mma8(float* d, const uint32_t* a, const uint32_t* b) {
    asm volatile(
        "mma.sync.aligned.m16n8k8.row.col.f32.tf32.tf32.f32 "
        "{%0,%1,%2,%3}, {%4,%5,%6,%7}, {%8,%9}, {%0,%1,%2,%3};"
        : "+f"(d[0]), "+f"(d[1]), "+f"(d[2]), "+f"(d[3])
        : "r"(a[0]), "r"(a[1]), "r"(a[2]), "r"(a[3]), "r"(b[0]), "r"(b[1]));
}

// ---------------------------------------------------------------------------
// QKV GEMM (single tf32): qkv[m][n] = sum_k W[m][k] * x[b][k][n]
// B read k-major directly from x (no pre-transpose). q,k rows written
// TRANSPOSED to g_qkT[b][n][c]; v rows written normally to g_v[b][c][n].
// Tile 64x64, 128 threads.
// ---------------------------------------------------------------------------
__global__ __launch_bounds__(128) void gemm_qkv(const float* __restrict__ W,
                                                const float* __restrict__ X)
{
    __shared__ float sm[4608];
    float* As = sm;          // 64 x 36  [m][k]
    float* Bs = sm + 2304;   // 32 x 72  [k][n]

    const int tid = threadIdx.x;
    const int bm = blockIdx.y * 64, bn = blockIdx.x * 64, b = blockIdx.z;
    const float* Xb = X + (size_t)b * 256 * 1024;

    const int lane = tid & 31, wrp = tid >> 5;
    const int g = lane >> 2, t = lane & 3;
    const int qb = wrp * 16;

    float cf[8][4] = {};

    for (int kc = 0; kc < 8; ++kc) {
        const int k0 = kc * 32;
        if (kc) __syncthreads();
        #pragma unroll
        for (int i = 0; i < 4; ++i) {
            const int m = (tid >> 3) + i * 16;
            const int kq = (tid & 7) * 4;
            float4 av = *(const float4*)&W[(size_t)(bm + m) * 256 + k0 + kq];
            av.x = tf(av.x); av.y = tf(av.y); av.z = tf(av.z); av.w = tf(av.w);
            *(float4*)&As[m * 36 + kq] = av;
            const int k = (tid >> 4) + i * 8;
            const int n4 = (tid & 15) * 4;
            float4 bv = *(const float4*)&Xb[(size_t)(k0 + k) * 1024 + bn + n4];
            bv.x = tf(bv.x); bv.y = tf(bv.y); bv.z = tf(bv.z); bv.w = tf(bv.w);
            *(float4*)&Bs[k * 72 + n4] = bv;
        }
        __syncthreads();

        #pragma unroll
        for (int kk = 0; kk < 4; ++kk) {
            const int r1 = (qb + g) * 36 + kk * 8 + t;
            const int r2 = r1 + 8 * 36;
            uint32_t a[4];
            a[0] = __float_as_uint(As[r1]);     a[1] = __float_as_uint(As[r2]);
            a[2] = __float_as_uint(As[r1 + 4]); a[3] = __float_as_uint(As[r2 + 4]);
            #pragma unroll
            for (int nt = 0; nt < 8; ++nt) {
                uint32_t bb[2];
                bb[0] = __float_as_uint(Bs[(kk * 8 + t) * 72 + nt * 8 + g]);
                bb[1] = __float_as_uint(Bs[(kk * 8 + t + 4) * 72 + nt * 8 + g]);
                mma8(cf[nt], a, bb);
            }
        }
    }
    __syncthreads();

    if (bm < 512) {
        // transposed epilogue: stage CsT[n][m] (ld 68), write qkT[b][n][c]
        float* CsT = sm;    // 64 x 68
        #pragma unroll
        for (int nt = 0; nt < 8; ++nt) {
            const int n0 = nt * 8 + 2 * t;
            CsT[(n0 + 0) * 68 + qb + g]     = cf[nt][0];
            CsT[(n0 + 1) * 68 + qb + g]     = cf[nt][1];
            CsT[(n0 + 0) * 68 + qb + g + 8] = cf[nt][2];
            CsT[(n0 + 1) * 68 + qb + g + 8] = cf[nt][3];
        }
        __syncthreads();
        #pragma unroll
        for (int i = 0; i < 8; ++i) {
            const int flat = i * 128 + tid;
            const int n = flat >> 4, m4 = (flat & 15) * 4;
            *(float4*)&g_qkT[((size_t)b * 1024 + bn + n) * 512 + bm + m4] =
                *(const float4*)&CsT[n * 68 + m4];
        }
    } else {
        // normal epilogue for v
        float* Cs = sm;     // 64 x 68
        const int row1 = qb + g, row2 = row1 + 8;
        #pragma unroll
        for (int nt = 0; nt < 8; ++nt) {
            *(float2*)&Cs[row1 * 68 + nt * 8 + 2 * t] = make_float2(cf[nt][0], cf[nt][1]);
            *(float2*)&Cs[row2 * 68 + nt * 8 + 2 * t] = make_float2(cf[nt][2], cf[nt][3]);
        }
        __syncthreads();
        #pragma unroll
        for (int i = 0; i < 8; ++i) {
            const int flat = i * 128 + tid;
            const int m = flat >> 4, n4 = (flat & 15) * 4;
            *(float4*)&g_v[((size_t)b * 256 + bm - 512 + m) * 1024 + bn + n4] =
                *(const float4*)&Cs[m * 68 + n4];
        }
    }
}

// ---------------------------------------------------------------------------
// Flash attention (single tf32 mma). Block = 64 queries of one (b,h), 128 thr.
// smem 44.5KB -> 5 CTA/SM. Out -> g_attT [b][n][256].
// ---------------------------------------------------------------------------
__global__ __launch_bounds__(128) void attn_kernel()
{
    __shared__ float Qs[64 * 36];   // [q][d]
    __shared__ float Ks[64 * 36];   // [m][d]
    __shared__ float Vs[32 * 68];   // [d][m]
    __shared__ float Ps[64 * 68];   // [q][m]; later O staging [q][d]

    const int tid = threadIdx.x;
    const int bh = blockIdx.y;
    const int b = bh >> 3, h = bh & 7;
    const int q0 = blockIdx.x * 64;

    const float* qkTb = g_qkT + (size_t)b * 1024 * 512;
    const float* vp   = g_v   + ((size_t)b * 256 + h * 32) * 1024;

    const int lane = tid & 31, wrp = tid >> 5;
    const int g = lane >> 2, t = lane & 3;
    const int qb = wrp * 16;

    // load Q once (scaled, tf32-rounded)
    #pragma unroll
    for (int i = 0; i < 4; ++i) {
        const int q = (tid >> 3) + i * 16;
        const int d4 = (tid & 7) * 4;
        float4 v = *(const float4*)&qkTb[(size_t)(q0 + q) * 512 + h * 32 + d4];
        v.x = tf(v.x * SCALE); v.y = tf(v.y * SCALE);
        v.z = tf(v.z * SCALE); v.w = tf(v.w * SCALE);
        *(float4*)&Qs[q * 36 + d4] = v;
    }

    float rm[2] = {-1e30f, -1e30f};
    float rs[2] = {0.0f, 0.0f};
    float oacc[4][4] = {};

    for (int mc = 0; mc < 16; ++mc) {
        const int m0 = mc * 64;
        __syncthreads();
        #pragma unroll
        for (int i = 0; i < 4; ++i) {
            const int m = (tid >> 3) + i * 16;
            const int d4 = (tid & 7) * 4;
            float4 v = *(const float4*)&qkTb[(size_t)(m0 + m) * 512 + 256 + h * 32 + d4];
            v.x = tf(v.x); v.y = tf(v.y); v.z = tf(v.z); v.w = tf(v.w);
            *(float4*)&Ks[m * 36 + d4] = v;
            const int d = (tid >> 4) + i * 8;
            const int m4 = (tid & 15) * 4;
            float4 w = *(const float4*)&vp[(size_t)d * 1024 + m0 + m4];
            w.x = tf(w.x); w.y = tf(w.y); w.z = tf(w.z); w.w = tf(w.w);
            *(float4*)&Vs[d * 68 + m4] = w;
        }
        __syncthreads();

        // S = Q K^T  (16q x 64m per warp)
        float sf[8][4] = {};
        #pragma unroll
        for (int kk = 0; kk < 4; ++kk) {
            const int r1 = (qb + g) * 36 + kk * 8 + t;
            const int r2 = r1 + 8 * 36;
            uint32_t a[4];
            a[0] = __float_as_uint(Qs[r1]);     a[1] = __float_as_uint(Qs[r2]);
            a[2] = __float_as_uint(Qs[r1 + 4]); a[3] = __float_as_uint(Qs[r2 + 4]);
            #pragma unroll
            for (int nt = 0; nt < 8; ++nt) {
                const int bb = (nt * 8 + g) * 36 + kk * 8 + t;
                uint32_t bf[2];
                bf[0] = __float_as_uint(Ks[bb]); bf[1] = __float_as_uint(Ks[bb + 4]);
                mma8(sf[nt], a, bf);
            }
        }

        // online softmax (rows qb+g and qb+g+8)
        float m1 = -1e30f, m2 = -1e30f;
        #pragma unroll
        for (int nt = 0; nt < 8; ++nt) {
            m1 = fmaxf(m1, fmaxf(sf[nt][0], sf[nt][1]));
            m2 = fmaxf(m2, fmaxf(sf[nt][2], sf[nt][3]));
        }
        m1 = fmaxf(m1, __shfl_xor_sync(0xffffffffu, m1, 1));
        m1 = fmaxf(m1, __shfl_xor_sync(0xffffffffu, m1, 2));
        m2 = fmaxf(m2, __shfl_xor_sync(0xffffffffu, m2, 1));
        m2 = fmaxf(m2, __shfl_xor_sync(0xffffffffu, m2, 2));
        const float nm1 = fmaxf(rm[0], m1), nm2 = fmaxf(rm[1], m2);
        const float f1 = __expf(rm[0] - nm1), f2 = __expf(rm[1] - nm2);
        rm[0] = nm1; rm[1] = nm2;
        float cs1 = 0.0f, cs2 = 0.0f;
        #pragma unroll
        for (int nt = 0; nt < 8; ++nt) {
            float p0 = __expf(sf[nt][0] - nm1);
            float p1 = __expf(sf[nt][1] - nm1);
            float p2 = __expf(sf[nt][2] - nm2);
            float p3 = __expf(sf[nt][3] - nm2);
            cs1 += p0 + p1; cs2 += p2 + p3;
            *(float2*)&Ps[(qb + g) * 68 + nt * 8 + 2 * t]     = make_float2(tf(p0), tf(p1));
            *(float2*)&Ps[(qb + g + 8) * 68 + nt * 8 + 2 * t] = make_float2(tf(p2), tf(p3));
        }
        cs1 += __shfl_xor_sync(0xffffffffu, cs1, 1);
        cs1 += __shfl_xor_sync(0xffffffffu, cs1, 2);
        cs2 += __shfl_xor_sync(0xffffffffu, cs2, 1);
        cs2 += __shfl_xor_sync(0xffffffffu, cs2, 2);
        rs[0] = rs[0] * f1 + cs1;
        rs[1] = rs[1] * f2 + cs2;
        #pragma unroll
        for (int nt = 0; nt < 4; ++nt) {
            oacc[nt][0] *= f1; oacc[nt][1] *= f1;
            oacc[nt][2] *= f2; oacc[nt][3] *= f2;
        }
        __syncwarp();

        // O += P V^T  (16q x 32d per warp)
        #pragma unroll
        for (int kk = 0; kk < 8; ++kk) {
            const int r1 = (qb + g) * 68 + kk * 8 + t;
            const int r2 = r1 + 8 * 68;
            uint32_t pa[4];
            pa[0] = __float_as_uint(Ps[r1]);     pa[1] = __float_as_uint(Ps[r2]);
            pa[2] = __float_as_uint(Ps[r1 + 4]); pa[3] = __float_as_uint(Ps[r2 + 4]);
            #pragma unroll
            for (int nt = 0; nt < 4; ++nt) {
                const int vb = (nt * 8 + g) * 68 + kk * 8 + t;
                uint32_t bf[2];
                bf[0] = __float_as_uint(Vs[vb]); bf[1] = __float_as_uint(Vs[vb + 4]);
                mma8(oacc[nt], pa, bf);
            }
        }
        __syncwarp();
    }

    // normalize + stage O[q][d] then coalesced store to attT
    __syncthreads();
    const float inv1 = 1.0f / rs[0], inv2 = 1.0f / rs[1];
    float* Os = Ps;   // 64 x 36
    #pragma unroll
    for (int nt = 0; nt < 4; ++nt) {
        *(float2*)&Os[(qb + g) * 36 + nt * 8 + 2 * t] =
            make_float2(oacc[nt][0] * inv1, oacc[nt][1] * inv1);
        *(float2*)&Os[(qb + g + 8) * 36 + nt * 8 + 2 * t] =
            make_float2(oacc[nt][2] * inv2, oacc[nt][3] * inv2);
    }
    __syncthreads();
    #pragma unroll
    for (int i = 0; i < 4; ++i) {
        const int flat = i * 128 + tid;
        const int q = flat >> 3, d4 = (flat & 7) * 4;
        *(float4*)&g_attT[((size_t)b * 1024 + q0 + q) * 256 + h * 32 + d4] =
            *(const float4*)&Os[q * 36 + d4];
    }
}

// ---------------------------------------------------------------------------
// LePE: attT[b][n][c] += dwconv5x5(v)[c][n] + lepe_b[c]
// ---------------------------------------------------------------------------
#define LEPE_SMEM (20160 * sizeof(float))
__global__ __launch_bounds__(256) void lepe_kernel(const float* __restrict__ lw,
                                                   const float* __restrict__ lb)
{
    extern __shared__ float ls[];
    float* sv  = ls;            // 64 x 289 (8 rows x 36 cols, c-stride 289)
    float* wch = ls + 64 * 289; // 64 x 25
    float* bch = wch + 1600;    // 64

    const int cg = blockIdx.x, rb = blockIdx.y, b = blockIdx.z;
    const int tid = threadIdx.x;

    for (int i = tid; i < 1600; i += 256) wch[i] = lw[cg * 64 * 25 + i];
    if (tid < 64) bch[tid] = lb[cg * 64 + tid];
    for (int i = tid; i < 64 * 8 * 4; i += 256) {
        const int c = i >> 5, rsd = (i >> 2) & 7, e = i & 3;
        const int col = (e < 2) ? e : 32 + e;
        sv[c * 289 + rsd * 36 + col] = 0.0f;
    }
    const float* vbase = g_v + ((size_t)b * 256 + cg * 64) * 1024;
    for (int i = tid; i < 4096; i += 256) {
        const int c = i >> 6, rsd = (i >> 3) & 7, q4 = (i & 7) * 4;
        const int gr = rb * 4 - 2 + rsd;
        float4 v = make_float4(0.f, 0.f, 0.f, 0.f);
        if ((unsigned)gr < 32u)
            v = *(const float4*)&vbase[(size_t)c * 1024 + gr * 32 + q4];
        float* p = &sv[c * 289 + rsd * 36 + 2 + q4];
        p[0] = v.x; p[1] = v.y; p[2] = v.z; p[3] = v.w;
    }
    __syncthreads();

    const int c = tid & 63, r = tid >> 6;
    const float* svc = &sv[c * 289];
    const float* wc = &wch[c * 25];
    const float bias = bch[c];
    float* op = g_attT + ((size_t)b * 1024 + (rb * 4 + r) * 32) * 256 + cg * 64 + c;
    for (int col = 0; col < 32; ++col) {
        float acc = bias;
        #pragma unroll
        for (int kh = 0; kh < 5; ++kh)
            #pragma unroll
            for (int kw = 0; kw < 5; ++kw)
                acc += wc[kh * 5 + kw] * svc[(r + kh) * 36 + col + kw];
        op[(size_t)col * 256] += acc;
    }
}

// ---------------------------------------------------------------------------
// Proj GEMM (single tf32): out[m][n] = sum_k W[m][k] * attT[b][n][k] + bias[m]
// ---------------------------------------------------------------------------
__global__ __launch_bounds__(128) void gemm_proj(const float* __restrict__ W,
                                                 const float* __restrict__ Bt,
                                                 float* __restrict__ C,
                                                 const float* __restrict__ bias)
{
    __shared__ float sm[4608];
    float* Ah = sm;          // 64 x 36  [m][k]
    float* Bh = sm + 2304;   // 64 x 36  [n][k]

    const int tid = threadIdx.x;
    const int bm = blockIdx.y * 64, bn = blockIdx.x * 64, b = blockIdx.z;
    const float* Btb = Bt + (size_t)b * 1024 * 256;
    float* Cb = C + (size_t)b * 256 * 1024;

    const int lane = tid & 31, wrp = tid >> 5;
    const int g = lane >> 2, t = lane & 3;
    const int qb = wrp * 16;

    float cf[8][4] = {};

    for (int kc = 0; kc < 8; ++kc) {
        const int k0 = kc * 32;
        if (kc) __syncthreads();
        #pragma unroll
        for (int i = 0; i < 4; ++i) {
            const int m = (tid >> 3) + i * 16;
            const int kq = (tid & 7) * 4;
            float4 av = *(const float4*)&W[(size_t)(bm + m) * 256 + k0 + kq];
            av.x = tf(av.x); av.y = tf(av.y); av.z = tf(av.z); av.w = tf(av.w);
            *(float4*)&Ah[m * 36 + kq] = av;
            float4 bv = *(const float4*)&Btb[(size_t)(bn + m) * 256 + k0 + kq];
            bv.x = tf(bv.x); bv.y = tf(bv.y); bv.z = tf(bv.z); bv.w = tf(bv.w);
            *(float4*)&Bh[m * 36 + kq] = bv;
        }
        __syncthreads();

        #pragma unroll
        for (int kk = 0; kk < 4; ++kk) {
            const int r1 = (qb + g) * 36 + kk * 8 + t;
            const int r2 = r1 + 8 * 36;
            uint32_t a[4];
            a[0] = __float_as_uint(Ah[r1]);     a[1] = __float_as_uint(Ah[r2]);
            a[2] = __float_as_uint(Ah[r1 + 4]); a[3] = __float_as_uint(Ah[r2 + 4]);
            #pragma unroll
            for (int nt = 0; nt < 8; ++nt) {
                const int bb = (nt * 8 + g) * 36 + kk * 8 + t;
                uint32_t bf[2];
                bf[0] = __float_as_uint(Bh[bb]); bf[1] = __float_as_uint(Bh[bb + 4]);
                mma8(cf[nt], a, bf);
            }
        }
    }
    __syncthreads();

    float* Cs = sm;   // 64 x 68
    const int row1 = qb + g, row2 = row1 + 8;
    const float bi1 = bias[bm + row1];
    const float bi2 = bias[bm + row2];
    #pragma unroll
    for (int nt = 0; nt < 8; ++nt) {
        *(float2*)&Cs[row1 * 68 + nt * 8 + 2 * t] = make_float2(cf[nt][0] + bi1, cf[nt][1] + bi1);
        *(float2*)&Cs[row2 * 68 + nt * 8 + 2 * t] = make_float2(cf[nt][2] + bi2, cf[nt][3] + bi2);
    }
    __syncthreads();
    #pragma unroll
    for (int i = 0; i < 8; ++i) {
        const int flat = i * 128 + tid;
        const int m = flat >> 4, n4 = (flat & 15) * 4;
        *(float4*)&Cb[(size_t)(bm + m) * 1024 + bn + n4] = *(const float4*)&Cs[m * 68 + n4];
    }
}

// ---------------------------------------------------------------------------
extern "C" void kernel_launch(void* const* d_in, const int* in_sizes, int n_in,
                              void* d_out, int out_size)
{
    const float* x      = (const float*)d_in[0];
    const float* qkv_w  = (const float*)d_in[1];
    const float* proj_w = (const float*)d_in[2];
    const float* proj_b = (const float*)d_in[3];
    const float* lepe_w = (const float*)d_in[4];
    const float* lepe_b = (const float*)d_in[5];
    float* out = (float*)d_out;

    float* attT_p;
    cudaGetSymbolAddress((void**)&attT_p, g_attT);

    cudaFuncSetAttribute(lepe_kernel, cudaFuncAttributeMaxDynamicSharedMemorySize, (int)LEPE_SMEM);

    // 1) qkv = qkv_w @ x  -> q,k transposed (g_qkT), v normal (g_v)
    gemm_qkv<<<dim3(16, 12, 8), 128>>>(qkv_w, x);
    // 2) attention -> attT
    attn_kernel<<<dim3(16, 64), 128>>>();
    // 3) LePE accumulate into attT
    lepe_kernel<<<dim3(4, 8, 8), 256, LEPE_SMEM>>>(lepe_w, lepe_b);
    // 4) out = proj_w @ att + proj_b
    gemm_proj<<<dim3(16, 4, 8), 128>>>(proj_w, attT_p, out, proj_b);
}